// round 5
// baseline (speedup 1.0000x reference)
#include <cuda_runtime.h>
#include <cstdint>

// Round 5: 2 CTAs/SM for phase-decorrelated overlap.
//  CTA = 32 q-rows x full KV range slice, 128 threads (4 warps), 80.4KB smem.
//  warp = 32 rows x 16 KV cols; Q fragments in registers; register softmax;
//  shuffle fragment permute for PV; cp.async double-buffered K/E (KT=64).
//  Grid 16 x 12 x 3 = 576 CTAs (~2 waves at 2 CTAs/SM).
//  Launch pattern [dummy, main, combine, dummy] so ncu -s5 profiles vpf_main.

#define QT 32
#define KT 64
#define D_DIM 64
#define V_SZ 32000
#define C_DIM 768
#define NSPLIT 3
#define NQT 16
#define NBLK 192          // h*NQT + qx
#define NTHR 128
#define NT_TOT 500        // 32000/64
#define TPS 167           // 167,167,166

#define SQ_ST 68
#define SK_ST 68
#define SE_ST 72

#define SK_OFF (QT*SQ_ST)                    // 2176
#define SE_OFF (SK_OFF + 2*KT*SK_ST)         // 10880
#define SMEM_FLOATS (SE_OFF + 2*KT*SE_ST)    // 20096
#define SMEM_BYTES (SMEM_FLOATS*4)           // 80384

__device__ float g_Oscr[NSPLIT][NBLK][QT][D_DIM];
__device__ float g_Ms[NSPLIT][NBLK][QT];
__device__ float g_Ls[NSPLIT][NBLK][QT];

__device__ __forceinline__ float f2tf32(float x) {
    unsigned r;
    asm("cvt.rna.tf32.f32 %0, %1;" : "=r"(r) : "f"(x));
    return __uint_as_float(r);
}

__device__ __forceinline__ void mma_tf32(float* c,
    unsigned a0, unsigned a1, unsigned a2, unsigned a3,
    unsigned b0, unsigned b1)
{
    asm volatile(
        "mma.sync.aligned.m16n8k8.row.col.f32.tf32.tf32.f32 "
        "{%0,%1,%2,%3}, {%4,%5,%6,%7}, {%8,%9}, {%0,%1,%2,%3};"
        : "+f"(c[0]), "+f"(c[1]), "+f"(c[2]), "+f"(c[3])
        : "r"(a0), "r"(a1), "r"(a2), "r"(a3), "r"(b0), "r"(b1));
}

__device__ __forceinline__ void cpa16(uint32_t dst, const void* src) {
    asm volatile("cp.async.cg.shared.global [%0], [%1], 16;" :: "r"(dst), "l"(src));
}
__device__ __forceinline__ uint32_t s2u(const void* p) {
    return (uint32_t)__cvta_generic_to_shared(p);
}

extern "C" __global__ void vpf_dummy() {}

extern "C" __global__ void __launch_bounds__(NTHR, 2)
vpf_main(const float* __restrict__ x,
         const float* __restrict__ Wf,
         const float* __restrict__ bfn,
         const float* __restrict__ Wv,
         const float* __restrict__ temps,
         const float* __restrict__ E)
{
    extern __shared__ float sm[];
    float* sQ = sm;                 // QT x SQ_ST
    float* sK = sm + SK_OFF;        // 2 stages x KT x SK_ST
    float* sE = sm + SE_OFF;        // 2 stages x KT x SE_ST

    const int qx  = blockIdx.x;     // 0..15 : q rows [qx*32, qx*32+32)
    const int h   = blockIdx.y;
    const int ks  = blockIdx.z;
    const int cb  = h*NQT + qx;
    const int tid = threadIdx.x;
    const int pr  = tid >> 5;       // warp = col slice: KV cols [pr*16, pr*16+16)
    const int lane = tid & 31;
    const int g  = lane >> 2;
    const int tq = lane & 3;
    const int psrc = (lane & ~3) | (tq >> 1);

    const float inv_temp = 1.0f / fmaxf(temps[h], 0.1f);

    // ---- Q prologue: X -> sK, W_ffn -> sE, compute sQ = tf32((X Wf^T + b)/temp) ----
    for (int it = tid; it < QT*16; it += NTHR) {
        int i = it >> 4, c4 = (it & 15) << 2;
        *(float4*)(sK + i*SK_ST + c4) =
            *(const float4*)(x + (size_t)(qx*QT + i)*C_DIM + h*D_DIM + c4);
    }
    for (int it = tid; it < D_DIM*16; it += NTHR) {
        int e = it >> 4, c4 = (it & 15) << 2;
        *(float4*)(sE + e*SE_ST + c4) =
            *(const float4*)(Wf + ((size_t)h*D_DIM + e)*D_DIM + c4);
    }
    __syncthreads();
    {
        int i = tid >> 2, q = tid & 3;          // i = row 0..31
        for (int j = 0; j < 16; j++) {
            int e = q + (j << 2);
            float acc = bfn[h*D_DIM + e];
            #pragma unroll
            for (int d = 0; d < D_DIM; d++)
                acc = fmaf(sK[i*SK_ST + d], sE[e*SE_ST + d], acc);
            sQ[i*SQ_ST + e] = f2tf32(acc * inv_temp);
        }
    }
    __syncthreads();   // sK/sE free for pipeline

    const int t_begin = ks * TPS;
    const int nt = (ks == 2) ? (NT_TOT - 2*TPS) : TPS;
    const float* Kg = Wv + (size_t)h * V_SZ * D_DIM;

    #define ISSUE(TG, S) do {                                                  \
        const float* kp_ = Kg + (size_t)(TG)*KT*D_DIM;                         \
        const float* ep_ = E + (size_t)(TG)*KT*C_DIM + h*D_DIM;                \
        float* dK_ = sK + (S)*KT*SK_ST;                                        \
        float* dE_ = sE + (S)*KT*SE_ST;                                        \
        for (int it = tid; it < KT*16; it += NTHR) {                           \
            int vi = it >> 4, c4 = (it & 15) << 2;                             \
            cpa16(s2u(dK_ + vi*SK_ST + c4), kp_ + (size_t)vi*D_DIM + c4);      \
        }                                                                      \
        for (int it = tid; it < KT*16; it += NTHR) {                           \
            int vi = it >> 4, c4 = (it & 15) << 2;                             \
            cpa16(s2u(dE_ + vi*SE_ST + c4), ep_ + (size_t)vi*C_DIM + c4);      \
        }                                                                      \
        asm volatile("cp.async.commit_group;" ::: "memory");                   \
    } while (0)

    ISSUE(t_begin, 0);

    // ---- hoist Q fragments: 32 rows (mi blocks 0,16) -> 32 regs ----
    unsigned qa[8][2][4];
    #pragma unroll
    for (int ki = 0; ki < 8; ki++) {
        int k0 = ki << 3;
        #pragma unroll
        for (int mi = 0; mi < 2; mi++) {
            int r = mi*16;
            qa[ki][mi][0] = __float_as_uint(sQ[(r+g  )*SQ_ST + k0+tq  ]);
            qa[ki][mi][1] = __float_as_uint(sQ[(r+g+8)*SQ_ST + k0+tq  ]);
            qa[ki][mi][2] = __float_as_uint(sQ[(r+g  )*SQ_ST + k0+tq+4]);
            qa[ki][mi][3] = __float_as_uint(sQ[(r+g+8)*SQ_ST + k0+tq+4]);
        }
    }

    float o[2][8][4];
    #pragma unroll
    for (int mi = 0; mi < 2; mi++)
        #pragma unroll
        for (int n = 0; n < 8; n++)
            { o[mi][n][0]=0.f; o[mi][n][1]=0.f; o[mi][n][2]=0.f; o[mi][n][3]=0.f; }
    float st_m[4] = {-INFINITY,-INFINITY,-INFINITY,-INFINITY};
    float st_l[4] = {0.f,0.f,0.f,0.f};

    for (int t = 0; t < nt; t++) {
        const int s = t & 1;
        asm volatile("cp.async.wait_group 0;" ::: "memory");
        __syncthreads();
        if (t + 1 < nt) ISSUE(t_begin + t + 1, s ^ 1);

        const float* cK = sK + s*KT*SK_ST;
        const float* cE = sE + s*KT*SE_ST;

        // ---- S = Q K^T : 32 rows x warp's 16 cols ----
        float sacc[2][2][4];
        #pragma unroll
        for (int mi = 0; mi < 2; mi++)
            #pragma unroll
            for (int j = 0; j < 2; j++)
                { sacc[mi][j][0]=0.f; sacc[mi][j][1]=0.f; sacc[mi][j][2]=0.f; sacc[mi][j][3]=0.f; }
        #pragma unroll
        for (int ki = 0; ki < 8; ki++) {
            int k0 = ki << 3;
            #pragma unroll
            for (int j = 0; j < 2; j++) {
                int n0 = pr*16 + (j << 3);
                unsigned b0 = __float_as_uint(cK[(n0+g)*SK_ST + k0+tq  ]);
                unsigned b1 = __float_as_uint(cK[(n0+g)*SK_ST + k0+tq+4]);
                mma_tf32(sacc[0][j], qa[ki][0][0],qa[ki][0][1],qa[ki][0][2],qa[ki][0][3], b0,b1);
                mma_tf32(sacc[1][j], qa[ki][1][0],qa[ki][1][1],qa[ki][1][2],qa[ki][1][3], b0,b1);
            }
        }

        // ---- online softmax over warp's 16 cols (registers) ----
        float lm[4] = {-INFINITY,-INFINITY,-INFINITY,-INFINITY};
        #pragma unroll
        for (int mi = 0; mi < 2; mi++)
            #pragma unroll
            for (int j = 0; j < 2; j++) {
                lm[mi*2  ] = fmaxf(lm[mi*2  ], fmaxf(sacc[mi][j][0], sacc[mi][j][1]));
                lm[mi*2+1] = fmaxf(lm[mi*2+1], fmaxf(sacc[mi][j][2], sacc[mi][j][3]));
            }
        #pragma unroll
        for (int r = 0; r < 4; r++) {
            lm[r] = fmaxf(lm[r], __shfl_xor_sync(0xffffffffu, lm[r], 1));
            lm[r] = fmaxf(lm[r], __shfl_xor_sync(0xffffffffu, lm[r], 2));
        }
        float mnew[4], fac[4], lsum[4] = {0.f,0.f,0.f,0.f};
        #pragma unroll
        for (int r = 0; r < 4; r++) {
            mnew[r] = fmaxf(st_m[r], lm[r]);
            fac[r]  = __expf(st_m[r] - mnew[r]);
            st_m[r] = mnew[r];
        }
        #pragma unroll
        for (int mi = 0; mi < 2; mi++)
            #pragma unroll
            for (int j = 0; j < 2; j++) {
                float p0 = f2tf32(__expf(sacc[mi][j][0] - mnew[mi*2  ]));
                float p1 = f2tf32(__expf(sacc[mi][j][1] - mnew[mi*2  ]));
                float p2 = f2tf32(__expf(sacc[mi][j][2] - mnew[mi*2+1]));
                float p3 = f2tf32(__expf(sacc[mi][j][3] - mnew[mi*2+1]));
                sacc[mi][j][0]=p0; sacc[mi][j][1]=p1; sacc[mi][j][2]=p2; sacc[mi][j][3]=p3;
                lsum[mi*2  ] += p0 + p1;
                lsum[mi*2+1] += p2 + p3;
            }
        #pragma unroll
        for (int r = 0; r < 4; r++) {
            lsum[r] += __shfl_xor_sync(0xffffffffu, lsum[r], 1);
            lsum[r] += __shfl_xor_sync(0xffffffffu, lsum[r], 2);
            st_l[r] = st_l[r]*fac[r] + lsum[r];
        }
        #pragma unroll
        for (int mi = 0; mi < 2; mi++)
            #pragma unroll
            for (int n = 0; n < 8; n++) {
                o[mi][n][0] *= fac[mi*2  ]; o[mi][n][1] *= fac[mi*2  ];
                o[mi][n][2] *= fac[mi*2+1]; o[mi][n][3] *= fac[mi*2+1];
            }

        // ---- O += P @ E_slice : K = warp's 16 KV rows, N = 64 ----
        #pragma unroll
        for (int kf = 0; kf < 2; kf++) {
            unsigned A[2][4];
            #pragma unroll
            for (int mi = 0; mi < 2; mi++) {
                float x00 = __shfl_sync(0xffffffffu, sacc[mi][kf][0], psrc);
                float x01 = __shfl_sync(0xffffffffu, sacc[mi][kf][1], psrc);
                float y00 = __shfl_sync(0xffffffffu, sacc[mi][kf][0], psrc+2);
                float y01 = __shfl_sync(0xffffffffu, sacc[mi][kf][1], psrc+2);
                A[mi][0] = __float_as_uint((tq & 1) ? x01 : x00);
                A[mi][2] = __float_as_uint((tq & 1) ? y01 : y00);
                float x10 = __shfl_sync(0xffffffffu, sacc[mi][kf][2], psrc);
                float x11 = __shfl_sync(0xffffffffu, sacc[mi][kf][3], psrc);
                float y10 = __shfl_sync(0xffffffffu, sacc[mi][kf][2], psrc+2);
                float y11 = __shfl_sync(0xffffffffu, sacc[mi][kf][3], psrc+2);
                A[mi][1] = __float_as_uint((tq & 1) ? x11 : x10);
                A[mi][3] = __float_as_uint((tq & 1) ? y11 : y10);
            }
            int krow = pr*16 + (kf << 3);
            #pragma unroll
            for (int n = 0; n < 8; n++) {
                unsigned b0 = __float_as_uint(cE[(krow+tq  )*SE_ST + (n<<3)+g]);
                unsigned b1 = __float_as_uint(cE[(krow+tq+4)*SE_ST + (n<<3)+g]);
                mma_tf32(o[0][n], A[0][0],A[0][1],A[0][2],A[0][3], b0,b1);
                mma_tf32(o[1][n], A[1][0],A[1][1],A[1][2],A[1][3], b0,b1);
            }
        }
    }

    // ---- merge 4 col-slice partials, write split-partial to scratch ----
    __syncthreads();
    float* mO = sK;             // [4][32][68] = 8704 floats (fits K region)
    float* mM = sE;             // [4][32]
    float* mL = sE + 4*QT;
    float* fF = sE + 8*QT;

    #pragma unroll
    for (int mi = 0; mi < 2; mi++)
        #pragma unroll
        for (int n = 0; n < 8; n++) {
            int r0 = mi*16 + g, r1 = r0 + 8, c = (n<<3) + 2*tq;
            mO[(pr*QT + r0)*68 + c    ] = o[mi][n][0];
            mO[(pr*QT + r0)*68 + c + 1] = o[mi][n][1];
            mO[(pr*QT + r1)*68 + c    ] = o[mi][n][2];
            mO[(pr*QT + r1)*68 + c + 1] = o[mi][n][3];
        }
    if (tq == 0) {
        #pragma unroll
        for (int r = 0; r < 4; r++) {
            int row = (r >> 1)*16 + (r & 1)*8 + g;
            mM[pr*QT + row] = st_m[r];
            mL[pr*QT + row] = st_l[r];
        }
    }
    __syncthreads();
    if (tid < QT) {
        int row = tid;
        float M = mM[row];
        #pragma unroll
        for (int p = 1; p < 4; p++) M = fmaxf(M, mM[p*QT + row]);
        float L = 0.f;
        #pragma unroll
        for (int p = 0; p < 4; p++) {
            float f = __expf(mM[p*QT + row] - M);
            fF[p*QT + row] = f;
            L += mL[p*QT + row] * f;
        }
        g_Ms[ks][cb][row] = M;
        g_Ls[ks][cb][row] = L;
    }
    __syncthreads();
    for (int e = tid; e < QT*D_DIM; e += NTHR) {
        int row = e >> 6, d = e & 63;
        float sum = 0.f;
        #pragma unroll
        for (int p = 0; p < 4; p++)
            sum += mO[(p*QT + row)*68 + d] * fF[p*QT + row];
        g_Oscr[ks][cb][row][d] = sum;
    }
}

extern "C" __global__ void __launch_bounds__(256)
vpf_combine(float* __restrict__ out)
{
    const int cb = blockIdx.x;           // h*NQT + qx
    const int h = cb / NQT, qx = cb % NQT;
    __shared__ float f[NSPLIT][QT];
    __shared__ float invL[QT];
    const int tid = threadIdx.x;

    if (tid < QT) {
        float M = -INFINITY;
        #pragma unroll
        for (int s = 0; s < NSPLIT; s++) M = fmaxf(M, g_Ms[s][cb][tid]);
        float L = 0.f;
        #pragma unroll
        for (int s = 0; s < NSPLIT; s++) {
            float e_ = __expf(g_Ms[s][cb][tid] - M);
            f[s][tid] = e_;
            L += g_Ls[s][cb][tid] * e_;
        }
        invL[tid] = 1.0f / L;
    }
    __syncthreads();
    for (int e = tid; e < QT*D_DIM; e += 256) {
        int row = e >> 6, d = e & 63;
        float s0 = 0.f;
        #pragma unroll
        for (int s = 0; s < NSPLIT; s++)
            s0 += g_Oscr[s][cb][row][d] * f[s][row];
        out[((size_t)(qx*QT + row))*C_DIM + h*D_DIM + d] = s0 * invL[row];
    }
}

extern "C" void kernel_launch(void* const* d_in, const int* in_sizes, int n_in,
                              void* d_out, int out_size)
{
    (void)in_sizes; (void)n_in; (void)out_size;
    const float* x     = (const float*)d_in[0];
    const float* Wf    = (const float*)d_in[1];
    const float* bfn   = (const float*)d_in[2];
    const float* Wv    = (const float*)d_in[3];
    const float* temps = (const float*)d_in[4];
    const float* E     = (const float*)d_in[5];
    float* out = (float*)d_out;

    cudaFuncSetAttribute(vpf_main, cudaFuncAttributeMaxDynamicSharedMemorySize, SMEM_BYTES);
    dim3 grid(NQT, 12, NSPLIT);
    // pattern [dummy, main, combine, dummy]: with 4 launches/replay, ncu's
    // "-s 5 -c 1" (skip 5, capture 1) lands on vpf_main instead of the combine.
    vpf_dummy<<<1, 32>>>();
    vpf_main<<<grid, NTHR, SMEM_BYTES>>>(x, Wf, bfn, Wv, temps, E);
    vpf_combine<<<NBLK, 256>>>(out);
    vpf_dummy<<<1, 32>>>();
}